// round 6
// baseline (speedup 1.0000x reference)
#include <cuda_runtime.h>

#define EMBED    1024
#define HEADS    16
#define HEAD_DIM 64
#define BATCH    4
#define SEQ      2048
#define M_TOT    (BATCH*SEQ)      // 8192 rows
#define BH       (BATCH*HEADS)    // 64 batch-heads

// ---------------- scratch (device globals: allocation-free) ----------------
__device__ float g_q[BH * SEQ * HEAD_DIM];     // [b,h,s,d], pre-scaled by 1/sqrt(D)
__device__ float g_k[BH * SEQ * HEAD_DIM];     // [b,h,s,d]
__device__ float g_v[BH * SEQ * HEAD_DIM];     // [b,h,s,d]
__device__ float g_attn[M_TOT * EMBED];        // [b,s,e]

// ---------------- SGEMM-NT: C[m,n] = sum_k A[m,k]*W[n,k] + bias[n] ----------
// MODE 0: scatter into [b,h,s,d] with scale (QKV projections)
// MODE 1: plain row-major [m,n] (output projection)
#define BM 128
#define BN 128
#define BK 8

template<int MODE>
__global__ __launch_bounds__(256) void sgemm_nt(
    const float* __restrict__ A, const float* __restrict__ W,
    const float* __restrict__ bias, float* __restrict__ C, float scale)
{
    __shared__ float As[BK][BM];
    __shared__ float Bs[BK][BN];

    const int tid = threadIdx.x;
    const int tx  = tid & 15;
    const int ty  = tid >> 4;
    const int row0 = blockIdx.y * BM;
    const int col0 = blockIdx.x * BN;

    const int lr = tid >> 1;          // 0..127
    const int lk = (tid & 1) * 4;     // 0 or 4

    const float* Ap = A + (size_t)row0 * EMBED;
    const float* Bp = W + (size_t)col0 * EMBED;

    float acc[8][8];
    #pragma unroll
    for (int i = 0; i < 8; i++)
        #pragma unroll
        for (int j = 0; j < 8; j++) acc[i][j] = 0.f;

    // software-pipelined: prefetch tile k0=0
    float4 a4 = *(const float4*)(Ap + lr * EMBED + lk);
    float4 b4 = *(const float4*)(Bp + lr * EMBED + lk);

    for (int k0 = 0; k0 < EMBED; k0 += BK) {
        __syncthreads();   // previous iteration's readers done
        As[lk+0][lr] = a4.x; As[lk+1][lr] = a4.y;
        As[lk+2][lr] = a4.z; As[lk+3][lr] = a4.w;
        Bs[lk+0][lr] = b4.x; Bs[lk+1][lr] = b4.y;
        Bs[lk+2][lr] = b4.z; Bs[lk+3][lr] = b4.w;
        __syncthreads();

        // issue next tile's loads BEFORE compute -> latency hidden by FMAs
        if (k0 + BK < EMBED) {
            a4 = *(const float4*)(Ap + lr * EMBED + k0 + BK + lk);
            b4 = *(const float4*)(Bp + lr * EMBED + k0 + BK + lk);
        }

        #pragma unroll
        for (int kk = 0; kk < BK; kk++) {
            float av[8], bv[8];
            *(float4*)(av)     = *(const float4*)&As[kk][ty*8];
            *(float4*)(av + 4) = *(const float4*)&As[kk][ty*8 + 4];
            *(float4*)(bv)     = *(const float4*)&Bs[kk][tx*8];
            *(float4*)(bv + 4) = *(const float4*)&Bs[kk][tx*8 + 4];
            #pragma unroll
            for (int i = 0; i < 8; i++)
                #pragma unroll
                for (int j = 0; j < 8; j++)
                    acc[i][j] = fmaf(av[i], bv[j], acc[i][j]);
        }
    }

    #pragma unroll
    for (int i = 0; i < 8; i++) {
        const int r = row0 + ty*8 + i;
        #pragma unroll
        for (int j = 0; j < 8; j++) {
            const int c = col0 + tx*8 + j;
            float v = acc[i][j] + bias[c];
            if (MODE == 0) {
                v *= scale;
                const int b = r / SEQ, s = r % SEQ;
                const int h = c / HEAD_DIM, d = c % HEAD_DIM;
                C[(((size_t)(b*HEADS + h))*SEQ + s)*HEAD_DIM + d] = v;
            } else {
                C[(size_t)r * EMBED + c] = v;
            }
        }
    }
}

// ---------------- Flash attention (causal), Br=Bc=64, D=64 -----------------
// Vectorized LDS.128 inner loops, conflict-free lane mapping:
//   thread (tx,ty): rows R0=ty*4+i, cols cj=tx+16j (lane stride = 1 smem row;
//   row pitch 68 floats = 17x16B units (odd) -> 8 lanes/phase hit 8 banks).
// V is stored TRANSPOSED (Vt[d][c]) so P and V are both read float4 over c.
#define PADW 68
#define FA_SMEM (4 * 64 * PADW * (int)sizeof(float))   // 69632 B

__global__ __launch_bounds__(256) void flash_attn_kernel(
    const float* __restrict__ Q, const float* __restrict__ K,
    const float* __restrict__ V, float* __restrict__ Out)
{
    extern __shared__ float sm[];
    float (*Qs)[PADW] = (float(*)[PADW])(sm);
    float (*Ks)[PADW] = (float(*)[PADW])(sm + 64*PADW);
    float (*Vt)[PADW] = (float(*)[PADW])(sm + 2*64*PADW);   // [d][c] transposed
    float (*Ps)[PADW] = (float(*)[PADW])(sm + 3*64*PADW);

    const int bh = blockIdx.y;
    const int qt = blockIdx.x;
    const int q0 = qt * 64;

    const float* Qb = Q + (size_t)bh * SEQ * HEAD_DIM;
    const float* Kb = K + (size_t)bh * SEQ * HEAD_DIM;
    const float* Vb = V + (size_t)bh * SEQ * HEAD_DIM;

    const int tid = threadIdx.x;
    const int tx = tid & 15;
    const int ty = tid >> 4;
    const int R0 = ty * 4;

    // loaders for Q/K (row-major float4)
    const int lrow = tid >> 4;          // 0..15
    const int lcol = (tid & 15) * 4;    // 0..60
    // loader for V transpose
    const int vd  = tid & 63;           // d index, consecutive within warp
    const int vcg = tid >> 6;           // 0..3

    // load Q tile
    #pragma unroll
    for (int rr = 0; rr < 64; rr += 16) {
        float4 v = *(const float4*)(Qb + (size_t)(q0 + lrow + rr) * HEAD_DIM + lcol);
        *(float4*)&Qs[lrow + rr][lcol] = v;
    }

    float m_i[4], l_i[4], o[4][4];
    #pragma unroll
    for (int i = 0; i < 4; i++) {
        m_i[i] = -1e30f; l_i[i] = 0.f;
        #pragma unroll
        for (int j = 0; j < 4; j++) o[i][j] = 0.f;
    }

    for (int kt = 0; kt <= qt; kt++) {
        __syncthreads();   // protect Ks/Vt/Ps from previous iteration readers

        // K tile: row-major
        #pragma unroll
        for (int rr = 0; rr < 64; rr += 16) {
            const size_t g = (size_t)(kt*64 + lrow + rr) * HEAD_DIM + lcol;
            *(float4*)&Ks[lrow + rr][lcol] = *(const float4*)(Kb + g);
        }
        // V tile: transposed. Gmem reads coalesced over vd (32 consecutive lanes),
        // STS.128 rows stride 1 per lane -> conflict-free.
        {
            const float* Vp = Vb + (size_t)(kt*64) * HEAD_DIM + vd;
            #pragma unroll
            for (int u = 0; u < 4; u++) {
                const int c = vcg*16 + u*4;
                float4 t;
                t.x = Vp[(size_t)(c+0) * HEAD_DIM];
                t.y = Vp[(size_t)(c+1) * HEAD_DIM];
                t.z = Vp[(size_t)(c+2) * HEAD_DIM];
                t.w = Vp[(size_t)(c+3) * HEAD_DIM];
                *(float4*)&Vt[vd][c] = t;
            }
        }
        __syncthreads();

        // scores S = Q K^T  (scale folded into Q), float4 over d
        float s[4][4];
        #pragma unroll
        for (int i = 0; i < 4; i++)
            #pragma unroll
            for (int j = 0; j < 4; j++) s[i][j] = 0.f;

        #pragma unroll 4
        for (int d0 = 0; d0 < 64; d0 += 4) {
            float4 qa[4], kb[4];
            #pragma unroll
            for (int i = 0; i < 4; i++) qa[i] = *(const float4*)&Qs[R0+i][d0];
            #pragma unroll
            for (int j = 0; j < 4; j++) kb[j] = *(const float4*)&Ks[tx + 16*j][d0];
            #pragma unroll
            for (int i = 0; i < 4; i++)
                #pragma unroll
                for (int j = 0; j < 4; j++) {
                    s[i][j] = fmaf(qa[i].x, kb[j].x, s[i][j]);
                    s[i][j] = fmaf(qa[i].y, kb[j].y, s[i][j]);
                    s[i][j] = fmaf(qa[i].z, kb[j].z, s[i][j]);
                    s[i][j] = fmaf(qa[i].w, kb[j].w, s[i][j]);
                }
        }

        if (kt == qt) {     // diagonal tile: causal mask (col = tx+16j, row = R0+i)
            #pragma unroll
            for (int i = 0; i < 4; i++)
                #pragma unroll
                for (int j = 0; j < 4; j++)
                    if (tx + 16*j > R0 + i) s[i][j] = -1e30f;
        }

        // online softmax (row owned by the 16 tx-lanes of this ty group)
        #pragma unroll
        for (int i = 0; i < 4; i++) {
            float mx = s[i][0];
            #pragma unroll
            for (int j = 1; j < 4; j++) mx = fmaxf(mx, s[i][j]);
            #pragma unroll
            for (int off = 1; off < 16; off <<= 1)
                mx = fmaxf(mx, __shfl_xor_sync(0xffffffffu, mx, off));
            const float mnew  = fmaxf(m_i[i], mx);
            const float alpha = __expf(m_i[i] - mnew);
            float rs = 0.f;
            #pragma unroll
            for (int j = 0; j < 4; j++) {
                const float p = __expf(s[i][j] - mnew);
                Ps[R0+i][tx + 16*j] = p;
                rs += p;
            }
            #pragma unroll
            for (int off = 1; off < 16; off <<= 1)
                rs += __shfl_xor_sync(0xffffffffu, rs, off);
            l_i[i] = l_i[i] * alpha + rs;
            m_i[i] = mnew;
            #pragma unroll
            for (int j = 0; j < 4; j++) o[i][j] *= alpha;
        }
        __syncthreads();

        // O += P @ V : float4 over c on both operands (V transposed)
        #pragma unroll 4
        for (int c0 = 0; c0 < 64; c0 += 4) {
            float4 pa[4], vb[4];
            #pragma unroll
            for (int i = 0; i < 4; i++) pa[i] = *(const float4*)&Ps[R0+i][c0];
            #pragma unroll
            for (int j = 0; j < 4; j++) vb[j] = *(const float4*)&Vt[tx + 16*j][c0];
            #pragma unroll
            for (int i = 0; i < 4; i++)
                #pragma unroll
                for (int j = 0; j < 4; j++) {
                    o[i][j] = fmaf(pa[i].x, vb[j].x, o[i][j]);
                    o[i][j] = fmaf(pa[i].y, vb[j].y, o[i][j]);
                    o[i][j] = fmaf(pa[i].z, vb[j].z, o[i][j]);
                    o[i][j] = fmaf(pa[i].w, vb[j].w, o[i][j]);
                }
        }
    }

    // write back to [b, s, h*64 + (tx+16j)]
    const int b = bh / HEADS, h = bh % HEADS;
    #pragma unroll
    for (int i = 0; i < 4; i++) {
        const int srow = q0 + R0 + i;
        const float inv = 1.0f / l_i[i];
        #pragma unroll
        for (int j = 0; j < 4; j++)
            Out[((size_t)(b*SEQ + srow))*EMBED + h*HEAD_DIM + tx + 16*j] = o[i][j] * inv;
    }
}

// ---------------------------------------------------------------------------
extern "C" void kernel_launch(void* const* d_in, const int* in_sizes, int n_in,
                              void* d_out, int out_size)
{
    const float* query  = (const float*)d_in[0];
    const float* key_in = (const float*)d_in[1];
    const float* value  = (const float*)d_in[2];
    // d_in[3] = causal mask (int32), known causal -> unused
    const float* Wq = (const float*)d_in[4];
    const float* bq = (const float*)d_in[5];
    const float* Wk = (const float*)d_in[6];
    const float* bk = (const float*)d_in[7];
    const float* Wv = (const float*)d_in[8];
    const float* bv = (const float*)d_in[9];
    const float* Wo = (const float*)d_in[10];
    const float* bo = (const float*)d_in[11];
    float* out = (float*)d_out;

    void *pq, *pk, *pv, *pa;
    cudaGetSymbolAddress(&pq, g_q);
    cudaGetSymbolAddress(&pk, g_k);
    cudaGetSymbolAddress(&pv, g_v);
    cudaGetSymbolAddress(&pa, g_attn);

    cudaFuncSetAttribute(flash_attn_kernel,
                         cudaFuncAttributeMaxDynamicSharedMemorySize, FA_SMEM);

    const dim3 gg(EMBED / BN, M_TOT / BM);   // (8, 64)
    const float qscale = 0.125f;             // 1/sqrt(HEAD_DIM)

    sgemm_nt<0><<<gg, 256>>>(query,  Wq, bq, (float*)pq, qscale);
    sgemm_nt<0><<<gg, 256>>>(key_in, Wk, bk, (float*)pk, 1.0f);
    sgemm_nt<0><<<gg, 256>>>(value,  Wv, bv, (float*)pv, 1.0f);

    flash_attn_kernel<<<dim3(SEQ/64, BH), 256, FA_SMEM>>>(
        (const float*)pq, (const float*)pk, (const float*)pv, (float*)pa);

    sgemm_nt<1><<<gg, 256>>>((const float*)pa, Wo, bo, out, 1.0f);
}

// round 9
// speedup vs baseline: 1.3994x; 1.3994x over previous
#include <cuda_runtime.h>

#define EMBED    1024
#define HEADS    16
#define HEAD_DIM 64
#define BATCH    4
#define SEQ      2048
#define M_TOT    (BATCH*SEQ)      // 8192 rows
#define BH       (BATCH*HEADS)    // 64 batch-heads

typedef unsigned long long u64;

// ---------------- packed f32x2 helpers (Blackwell FFMA2 path) --------------
__device__ __forceinline__ u64 pk2(float x, float y) {
    u64 r; asm("mov.b64 %0, {%1, %2};" : "=l"(r) : "f"(x), "f"(y)); return r;
}
__device__ __forceinline__ void upk2(float& x, float& y, u64 v) {
    asm("mov.b64 {%0, %1}, %2;" : "=f"(x), "=f"(y) : "l"(v));
}
__device__ __forceinline__ void ffma2(u64& d, u64 a, u64 b) {
    asm("fma.rn.f32x2 %0, %1, %2, %0;" : "+l"(d) : "l"(a), "l"(b));
}
__device__ __forceinline__ float hadd2(u64 v) {
    float x, y; upk2(x, y, v); return x + y;
}

// ---------------- scratch (device globals: allocation-free) ----------------
__device__ float g_q[BH * SEQ * HEAD_DIM];     // [b,h,s,d], pre-scaled by 1/sqrt(D)
__device__ float g_k[BH * SEQ * HEAD_DIM];     // [b,h,s,d]
__device__ float g_v[BH * SEQ * HEAD_DIM];     // [b,h,s,d]
__device__ float g_attn[M_TOT * EMBED];        // [b,s,e]

// ---------------- SGEMM-NT: C[m,n] = sum_k A[m,k]*W[n,k] + bias[n] ----------
// MODE 0: scatter into [b,h,s,d] with scale (QKV projections)
// MODE 1: plain row-major [m,n] (output projection)
// A stored duplicated (a,a) in smem -> FFMA2 broadcast operand with no MOVs.
#define BM 128
#define BN 128
#define BK 8

template<int MODE>
__global__ __launch_bounds__(256) void sgemm_nt(
    const float* __restrict__ A, const float* __restrict__ W,
    const float* __restrict__ bias, float* __restrict__ C, float scale)
{
    __shared__ float2 As2[BK][BM];   // duplicated pairs (a,a): 8 KB
    __shared__ float  Bs [BK][BN];   // 4 KB

    const int tid = threadIdx.x;
    const int tx  = tid & 15;
    const int ty  = tid >> 4;
    const int row0 = blockIdx.y * BM;
    const int col0 = blockIdx.x * BN;

    const int lr = tid >> 1;          // 0..127
    const int lk = (tid & 1) * 4;     // 0 or 4

    const float* Ap = A + (size_t)row0 * EMBED;
    const float* Bp = W + (size_t)col0 * EMBED;

    u64 acc[8][4];                    // packed over j: (j=2jp, 2jp+1)
    #pragma unroll
    for (int i = 0; i < 8; i++)
        #pragma unroll
        for (int jp = 0; jp < 4; jp++) acc[i][jp] = 0ull;

    for (int k0 = 0; k0 < EMBED; k0 += BK) {
        float4 a4 = *(const float4*)(Ap + lr * EMBED + k0 + lk);
        float4 b4 = *(const float4*)(Bp + lr * EMBED + k0 + lk);
        __syncthreads();
        As2[lk+0][lr] = make_float2(a4.x, a4.x);
        As2[lk+1][lr] = make_float2(a4.y, a4.y);
        As2[lk+2][lr] = make_float2(a4.z, a4.z);
        As2[lk+3][lr] = make_float2(a4.w, a4.w);
        Bs[lk+0][lr] = b4.x; Bs[lk+1][lr] = b4.y;
        Bs[lk+2][lr] = b4.z; Bs[lk+3][lr] = b4.w;
        __syncthreads();

        #pragma unroll
        for (int kk = 0; kk < BK; kk++) {
            u64 avu[8];
            #pragma unroll
            for (int i = 0; i < 8; i++) {
                float2 t = As2[kk][ty*8 + i];   // LDS.64 broadcast
                avu[i] = pk2(t.x, t.y);
            }
            float4 blo = *(const float4*)&Bs[kk][tx*8];
            float4 bhi = *(const float4*)&Bs[kk][tx*8 + 4];
            u64 bvu[4];
            bvu[0] = pk2(blo.x, blo.y);
            bvu[1] = pk2(blo.z, blo.w);
            bvu[2] = pk2(bhi.x, bhi.y);
            bvu[3] = pk2(bhi.z, bhi.w);
            #pragma unroll
            for (int i = 0; i < 8; i++)
                #pragma unroll
                for (int jp = 0; jp < 4; jp++)
                    ffma2(acc[i][jp], avu[i], bvu[jp]);
        }
    }

    #pragma unroll
    for (int i = 0; i < 8; i++) {
        const int r = row0 + ty*8 + i;
        #pragma unroll
        for (int jp = 0; jp < 4; jp++) {
            float v0, v1;
            upk2(v0, v1, acc[i][jp]);
            #pragma unroll
            for (int u = 0; u < 2; u++) {
                const int c = col0 + tx*8 + 2*jp + u;
                float v = (u ? v1 : v0) + bias[c];
                if (MODE == 0) {
                    v *= scale;
                    const int b = r / SEQ, s = r % SEQ;
                    const int h = c / HEAD_DIM, d = c % HEAD_DIM;
                    C[(((size_t)(b*HEADS + h))*SEQ + s)*HEAD_DIM + d] = v;
                } else {
                    C[(size_t)r * EMBED + c] = v;
                }
            }
        }
    }
}

// ---------------- Flash attention (causal), Br=Bc=64, D=64 -----------------
// LDS.128 conflict-free mapping (cols cj = tx+16j; pitch 68 floats = odd*16B).
// V transposed in smem. Inner products packed f32x2 over the reduction dim
// (d for QK^T, c for P.V) -> free packing, one horizontal add per tile.
#define PADW 68
#define FA_SMEM (4 * 64 * PADW * (int)sizeof(float))   // 69632 B

__global__ __launch_bounds__(256) void flash_attn_kernel(
    const float* __restrict__ Q, const float* __restrict__ K,
    const float* __restrict__ V, float* __restrict__ Out)
{
    extern __shared__ float sm[];
    float (*Qs)[PADW] = (float(*)[PADW])(sm);
    float (*Ks)[PADW] = (float(*)[PADW])(sm + 64*PADW);
    float (*Vt)[PADW] = (float(*)[PADW])(sm + 2*64*PADW);   // [d][c] transposed
    float (*Ps)[PADW] = (float(*)[PADW])(sm + 3*64*PADW);

    const int bh = blockIdx.y;
    const int qt = blockIdx.x;
    const int q0 = qt * 64;

    const float* Qb = Q + (size_t)bh * SEQ * HEAD_DIM;
    const float* Kb = K + (size_t)bh * SEQ * HEAD_DIM;
    const float* Vb = V + (size_t)bh * SEQ * HEAD_DIM;

    const int tid = threadIdx.x;
    const int tx = tid & 15;
    const int ty = tid >> 4;
    const int R0 = ty * 4;

    // loaders for Q/K (row-major float4)
    const int lrow = tid >> 4;          // 0..15
    const int lcol = (tid & 15) * 4;    // 0..60
    // loader for V transpose
    const int vd  = tid & 63;           // d index, consecutive within warp
    const int vcg = tid >> 6;           // 0..3

    // load Q tile
    #pragma unroll
    for (int rr = 0; rr < 64; rr += 16) {
        float4 v = *(const float4*)(Qb + (size_t)(q0 + lrow + rr) * HEAD_DIM + lcol);
        *(float4*)&Qs[lrow + rr][lcol] = v;
    }

    float m_i[4], l_i[4], o[4][4];
    #pragma unroll
    for (int i = 0; i < 4; i++) {
        m_i[i] = -1e30f; l_i[i] = 0.f;
        #pragma unroll
        for (int j = 0; j < 4; j++) o[i][j] = 0.f;
    }

    for (int kt = 0; kt <= qt; kt++) {
        __syncthreads();   // protect Ks/Vt/Ps from previous iteration readers

        // K tile: row-major
        #pragma unroll
        for (int rr = 0; rr < 64; rr += 16) {
            const size_t g = (size_t)(kt*64 + lrow + rr) * HEAD_DIM + lcol;
            *(float4*)&Ks[lrow + rr][lcol] = *(const float4*)(Kb + g);
        }
        // V tile: transposed. Gmem reads coalesced over vd (32 consecutive lanes).
        {
            const float* Vp = Vb + (size_t)(kt*64) * HEAD_DIM + vd;
            #pragma unroll
            for (int u = 0; u < 4; u++) {
                const int c = vcg*16 + u*4;
                float4 t;
                t.x = Vp[(size_t)(c+0) * HEAD_DIM];
                t.y = Vp[(size_t)(c+1) * HEAD_DIM];
                t.z = Vp[(size_t)(c+2) * HEAD_DIM];
                t.w = Vp[(size_t)(c+3) * HEAD_DIM];
                *(float4*)&Vt[vd][c] = t;
            }
        }
        __syncthreads();

        // scores S = Q K^T, packed f32x2 over d
        u64 s2[4][4];
        #pragma unroll
        for (int i = 0; i < 4; i++)
            #pragma unroll
            for (int j = 0; j < 4; j++) s2[i][j] = 0ull;

        #pragma unroll 4
        for (int d0 = 0; d0 < 64; d0 += 4) {
            float4 qa[4], kb[4];
            #pragma unroll
            for (int i = 0; i < 4; i++) qa[i] = *(const float4*)&Qs[R0+i][d0];
            #pragma unroll
            for (int j = 0; j < 4; j++) kb[j] = *(const float4*)&Ks[tx + 16*j][d0];
            u64 qu[4][2], ku[4][2];
            #pragma unroll
            for (int i = 0; i < 4; i++) {
                qu[i][0] = pk2(qa[i].x, qa[i].y);
                qu[i][1] = pk2(qa[i].z, qa[i].w);
            }
            #pragma unroll
            for (int j = 0; j < 4; j++) {
                ku[j][0] = pk2(kb[j].x, kb[j].y);
                ku[j][1] = pk2(kb[j].z, kb[j].w);
            }
            #pragma unroll
            for (int i = 0; i < 4; i++)
                #pragma unroll
                for (int j = 0; j < 4; j++) {
                    ffma2(s2[i][j], qu[i][0], ku[j][0]);
                    ffma2(s2[i][j], qu[i][1], ku[j][1]);
                }
        }

        float s[4][4];
        #pragma unroll
        for (int i = 0; i < 4; i++)
            #pragma unroll
            for (int j = 0; j < 4; j++) s[i][j] = hadd2(s2[i][j]);

        if (kt == qt) {     // diagonal tile: causal mask (col = tx+16j, row = R0+i)
            #pragma unroll
            for (int i = 0; i < 4; i++)
                #pragma unroll
                for (int j = 0; j < 4; j++)
                    if (tx + 16*j > R0 + i) s[i][j] = -1e30f;
        }

        // online softmax (row owned by the 16 tx-lanes of this ty group)
        #pragma unroll
        for (int i = 0; i < 4; i++) {
            float mx = s[i][0];
            #pragma unroll
            for (int j = 1; j < 4; j++) mx = fmaxf(mx, s[i][j]);
            #pragma unroll
            for (int off = 1; off < 16; off <<= 1)
                mx = fmaxf(mx, __shfl_xor_sync(0xffffffffu, mx, off));
            const float mnew  = fmaxf(m_i[i], mx);
            const float alpha = __expf(m_i[i] - mnew);
            float rs = 0.f;
            #pragma unroll
            for (int j = 0; j < 4; j++) {
                const float p = __expf(s[i][j] - mnew);
                Ps[R0+i][tx + 16*j] = p;
                rs += p;
            }
            #pragma unroll
            for (int off = 1; off < 16; off <<= 1)
                rs += __shfl_xor_sync(0xffffffffu, rs, off);
            l_i[i] = l_i[i] * alpha + rs;
            m_i[i] = mnew;
            #pragma unroll
            for (int j = 0; j < 4; j++) o[i][j] *= alpha;
        }
        __syncthreads();

        // O += P @ V : packed f32x2 over c (V transposed)
        u64 ot2[4][4];
        #pragma unroll
        for (int i = 0; i < 4; i++)
            #pragma unroll
            for (int j = 0; j < 4; j++) ot2[i][j] = 0ull;

        #pragma unroll 4
        for (int c0 = 0; c0 < 64; c0 += 4) {
            float4 pa[4], vb[4];
            #pragma unroll
            for (int i = 0; i < 4; i++) pa[i] = *(const float4*)&Ps[R0+i][c0];
            #pragma unroll
            for (int j = 0; j < 4; j++) vb[j] = *(const float4*)&Vt[tx + 16*j][c0];
            u64 pu[4][2], vu[4][2];
            #pragma unroll
            for (int i = 0; i < 4; i++) {
                pu[i][0] = pk2(pa[i].x, pa[i].y);
                pu[i][1] = pk2(pa[i].z, pa[i].w);
            }
            #pragma unroll
            for (int j = 0; j < 4; j++) {
                vu[j][0] = pk2(vb[j].x, vb[j].y);
                vu[j][1] = pk2(vb[j].z, vb[j].w);
            }
            #pragma unroll
            for (int i = 0; i < 4; i++)
                #pragma unroll
                for (int j = 0; j < 4; j++) {
                    ffma2(ot2[i][j], pu[i][0], vu[j][0]);
                    ffma2(ot2[i][j], pu[i][1], vu[j][1]);
                }
        }
        #pragma unroll
        for (int i = 0; i < 4; i++)
            #pragma unroll
            for (int j = 0; j < 4; j++) o[i][j] += hadd2(ot2[i][j]);
    }

    // write back to [b, s, h*64 + (tx+16j)]
    const int b = bh / HEADS, h = bh % HEADS;
    #pragma unroll
    for (int i = 0; i < 4; i++) {
        const int srow = q0 + R0 + i;
        const float inv = 1.0f / l_i[i];
        #pragma unroll
        for (int j = 0; j < 4; j++)
            Out[((size_t)(b*SEQ + srow))*EMBED + h*HEAD_DIM + tx + 16*j] = o[i][j] * inv;
    }
}

// ---------------------------------------------------------------------------
extern "C" void kernel_launch(void* const* d_in, const int* in_sizes, int n_in,
                              void* d_out, int out_size)
{
    const float* query  = (const float*)d_in[0];
    const float* key_in = (const float*)d_in[1];
    const float* value  = (const float*)d_in[2];
    // d_in[3] = causal mask (int32), known causal -> unused
    const float* Wq = (const float*)d_in[4];
    const float* bq = (const float*)d_in[5];
    const float* Wk = (const float*)d_in[6];
    const float* bk = (const float*)d_in[7];
    const float* Wv = (const float*)d_in[8];
    const float* bv = (const float*)d_in[9];
    const float* Wo = (const float*)d_in[10];
    const float* bo = (const float*)d_in[11];
    float* out = (float*)d_out;

    void *pq, *pk, *pv, *pa;
    cudaGetSymbolAddress(&pq, g_q);
    cudaGetSymbolAddress(&pk, g_k);
    cudaGetSymbolAddress(&pv, g_v);
    cudaGetSymbolAddress(&pa, g_attn);

    cudaFuncSetAttribute(flash_attn_kernel,
                         cudaFuncAttributeMaxDynamicSharedMemorySize, FA_SMEM);

    const dim3 gg(EMBED / BN, M_TOT / BM);   // (8, 64)
    const float qscale = 0.125f;             // 1/sqrt(HEAD_DIM)

    sgemm_nt<0><<<gg, 256>>>(query,  Wq, bq, (float*)pq, qscale);
    sgemm_nt<0><<<gg, 256>>>(key_in, Wk, bk, (float*)pk, 1.0f);
    sgemm_nt<0><<<gg, 256>>>(value,  Wv, bv, (float*)pv, 1.0f);

    flash_attn_kernel<<<dim3(SEQ/64, BH), 256, FA_SMEM>>>(
        (const float*)pq, (const float*)pk, (const float*)pv, (float*)pa);

    sgemm_nt<1><<<gg, 256>>>((const float*)pa, Wo, bo, out, 1.0f);
}

// round 10
// speedup vs baseline: 3.0416x; 2.1736x over previous
#include <cuda_runtime.h>

#define EMBED    1024
#define HEADS    16
#define HEAD_DIM 64
#define BATCH    4
#define SEQ      2048
#define M_TOT    (BATCH*SEQ)      // 8192 rows
#define BH       (BATCH*HEADS)    // 64 batch-heads

typedef unsigned long long u64;
typedef unsigned int u32;

// ---------------- packed f32x2 helpers (Blackwell FFMA2 path) --------------
__device__ __forceinline__ u64 pk2(float x, float y) {
    u64 r; asm("mov.b64 %0, {%1, %2};" : "=l"(r) : "f"(x), "f"(y)); return r;
}
__device__ __forceinline__ void upk2(float& x, float& y, u64 v) {
    asm("mov.b64 {%0, %1}, %2;" : "=f"(x), "=f"(y) : "l"(v));
}
__device__ __forceinline__ void ffma2(u64& d, u64 a, u64 b) {
    asm("fma.rn.f32x2 %0, %1, %2, %0;" : "+l"(d) : "l"(a), "l"(b));
}
__device__ __forceinline__ float hadd2(u64 v) {
    float x, y; upk2(x, y, v); return x + y;
}

// ---------------- tf32 helpers ---------------------------------------------
__device__ __forceinline__ u32 f2tf32(float x) {
    u32 r; asm("cvt.rna.tf32.f32 %0, %1;" : "=r"(r) : "f"(x)); return r;
}
__device__ __forceinline__ void mma_tf32(float* d, const u32* a, const u32* b) {
    asm volatile(
        "mma.sync.aligned.m16n8k8.row.col.f32.tf32.tf32.f32 "
        "{%0,%1,%2,%3}, {%4,%5,%6,%7}, {%8,%9}, {%0,%1,%2,%3};"
        : "+f"(d[0]), "+f"(d[1]), "+f"(d[2]), "+f"(d[3])
        : "r"(a[0]), "r"(a[1]), "r"(a[2]), "r"(a[3]), "r"(b[0]), "r"(b[1]));
}
__device__ __forceinline__ void cpa16(void* sdst, const void* gsrc) {
    u32 s = (u32)__cvta_generic_to_shared(sdst);
    asm volatile("cp.async.ca.shared.global [%0], [%1], 16;" :: "r"(s), "l"(gsrc));
}

// ---------------- scratch (device globals: allocation-free) ----------------
__device__ float g_q[BH * SEQ * HEAD_DIM];     // [b,h,s,d], pre-scaled by 1/sqrt(D)
__device__ float g_k[BH * SEQ * HEAD_DIM];     // [b,h,s,d]
__device__ float g_v[BH * SEQ * HEAD_DIM];     // [b,h,s,d]
__device__ float g_attn[M_TOT * EMBED];        // [b,s,e]

// ---------------- tf32 tensor-core GEMM-NT ---------------------------------
// C[m,n] = sum_k A[m,k]*W[n,k] + bias[n]
// MODE 0: scatter into [b,h,s,d] with scale (QKV proj); MODE 1: row-major out.
// 128x128x16 tiles, cp.async double buffer, 8 warps (2x4), 4x4 m16n8k8 tiles.
#define GBM 128
#define GBN 128
#define GBK 16
#define GP  20                     // smem row pitch (floats): 20g mod 32 bijective
#define GNT (EMBED / GBK)          // 64 k-tiles

template<int MODE>
__global__ __launch_bounds__(256, 2) void sgemm_tf32(
    const float* __restrict__ A, const float* __restrict__ W,
    const float* __restrict__ bias, float* __restrict__ C, float scale)
{
    __shared__ float As[2][GBM][GP];   // 10240 B per stage
    __shared__ float Bs[2][GBN][GP];

    const int tid  = threadIdx.x;
    const int wid  = tid >> 5;
    const int lane = tid & 31;
    const int g    = lane >> 2;        // 0..7
    const int t4   = lane & 3;         // 0..3
    const int wm   = wid >> 2;         // 0..1
    const int wn   = wid & 3;          // 0..3
    const int m_base = wm * 64;
    const int n_base = wn * 32;

    const int row_blk = blockIdx.y * GBM;
    const int col_blk = blockIdx.x * GBN;

    const float* Ag = A + (size_t)row_blk * EMBED;
    const float* Bg = W + (size_t)col_blk * EMBED;

    const int cr = tid >> 2;           // 0..63
    const int cc = (tid & 3) * 4;      // 0,4,8,12

    float acc[4][4][4];
    #pragma unroll
    for (int mt = 0; mt < 4; mt++)
        #pragma unroll
        for (int nt = 0; nt < 4; nt++)
            #pragma unroll
            for (int r = 0; r < 4; r++) acc[mt][nt][r] = 0.f;

    // ---- prologue: stage 0 ----
    {
        const float* ap = Ag + (size_t)cr * EMBED + cc;
        const float* bp = Bg + (size_t)cr * EMBED + cc;
        cpa16(&As[0][cr][cc],      ap);
        cpa16(&As[0][cr + 64][cc], ap + (size_t)64 * EMBED);
        cpa16(&Bs[0][cr][cc],      bp);
        cpa16(&Bs[0][cr + 64][cc], bp + (size_t)64 * EMBED);
        asm volatile("cp.async.commit_group;" ::: "memory");
    }

    for (int t = 0; t < GNT; t++) {
        const int s = t & 1;
        if (t + 1 < GNT) {
            const int sn = (t + 1) & 1;
            const float* ap = Ag + (size_t)cr * EMBED + (t + 1) * GBK + cc;
            const float* bp = Bg + (size_t)cr * EMBED + (t + 1) * GBK + cc;
            cpa16(&As[sn][cr][cc],      ap);
            cpa16(&As[sn][cr + 64][cc], ap + (size_t)64 * EMBED);
            cpa16(&Bs[sn][cr][cc],      bp);
            cpa16(&Bs[sn][cr + 64][cc], bp + (size_t)64 * EMBED);
            asm volatile("cp.async.commit_group;" ::: "memory");
            asm volatile("cp.async.wait_group 1;" ::: "memory");
        } else {
            asm volatile("cp.async.wait_group 0;" ::: "memory");
        }
        __syncthreads();

        #pragma unroll
        for (int kk = 0; kk < GBK; kk += 8) {
            u32 a[4][4], b[4][2];
            #pragma unroll
            for (int mt = 0; mt < 4; mt++) {
                const float* p = &As[s][m_base + mt*16 + g][kk + t4];
                a[mt][0] = f2tf32(p[0]);
                a[mt][1] = f2tf32(p[8 * GP]);
                a[mt][2] = f2tf32(p[4]);
                a[mt][3] = f2tf32(p[8 * GP + 4]);
            }
            #pragma unroll
            for (int nt = 0; nt < 4; nt++) {
                const float* p = &Bs[s][n_base + nt*8 + g][kk + t4];
                b[nt][0] = f2tf32(p[0]);
                b[nt][1] = f2tf32(p[4]);
            }
            #pragma unroll
            for (int mt = 0; mt < 4; mt++)
                #pragma unroll
                for (int nt = 0; nt < 4; nt++)
                    mma_tf32(acc[mt][nt], a[mt], b[nt]);
        }
        __syncthreads();
    }

    // ---- epilogue: d0:(g,2t4) d1:(g,2t4+1) d2:(g+8,2t4) d3:(g+8,2t4+1) ----
    #pragma unroll
    for (int mt = 0; mt < 4; mt++) {
        #pragma unroll
        for (int nt = 0; nt < 4; nt++) {
            const int c0 = col_blk + n_base + nt*8 + 2*t4;
            const float bia0 = bias[c0], bia1 = bias[c0 + 1];
            #pragma unroll
            for (int half = 0; half < 2; half++) {
                const int r = row_blk + m_base + mt*16 + g + half*8;
                float v0 = acc[mt][nt][half*2 + 0] + bia0;
                float v1 = acc[mt][nt][half*2 + 1] + bia1;
                if (MODE == 0) {
                    v0 *= scale; v1 *= scale;
                    const int bb = r / SEQ, ss = r % SEQ;
                    const int h = c0 / HEAD_DIM, d = c0 % HEAD_DIM;
                    float* dst = &((float*)C)[(((size_t)(bb*HEADS + h))*SEQ + ss)*HEAD_DIM + d];
                    *(float2*)dst = make_float2(v0, v1);
                } else {
                    *(float2*)&C[(size_t)r * EMBED + c0] = make_float2(v0, v1);
                }
            }
        }
    }
}

// ---------------- Flash attention (causal), Br=Bc=64, D=64 -----------------
// (unchanged from R9 — measured good; FFMA2 inner products, LDS.128 mapping)
#define PADW 68
#define FA_SMEM (4 * 64 * PADW * (int)sizeof(float))   // 69632 B

__global__ __launch_bounds__(256) void flash_attn_kernel(
    const float* __restrict__ Q, const float* __restrict__ K,
    const float* __restrict__ V, float* __restrict__ Out)
{
    extern __shared__ float sm[];
    float (*Qs)[PADW] = (float(*)[PADW])(sm);
    float (*Ks)[PADW] = (float(*)[PADW])(sm + 64*PADW);
    float (*Vt)[PADW] = (float(*)[PADW])(sm + 2*64*PADW);   // [d][c] transposed
    float (*Ps)[PADW] = (float(*)[PADW])(sm + 3*64*PADW);

    const int bh = blockIdx.y;
    const int qt = blockIdx.x;
    const int q0 = qt * 64;

    const float* Qb = Q + (size_t)bh * SEQ * HEAD_DIM;
    const float* Kb = K + (size_t)bh * SEQ * HEAD_DIM;
    const float* Vb = V + (size_t)bh * SEQ * HEAD_DIM;

    const int tid = threadIdx.x;
    const int tx = tid & 15;
    const int ty = tid >> 4;
    const int R0 = ty * 4;

    const int lrow = tid >> 4;          // 0..15
    const int lcol = (tid & 15) * 4;    // 0..60
    const int vd  = tid & 63;           // d index, consecutive within warp
    const int vcg = tid >> 6;           // 0..3

    #pragma unroll
    for (int rr = 0; rr < 64; rr += 16) {
        float4 v = *(const float4*)(Qb + (size_t)(q0 + lrow + rr) * HEAD_DIM + lcol);
        *(float4*)&Qs[lrow + rr][lcol] = v;
    }

    float m_i[4], l_i[4], o[4][4];
    #pragma unroll
    for (int i = 0; i < 4; i++) {
        m_i[i] = -1e30f; l_i[i] = 0.f;
        #pragma unroll
        for (int j = 0; j < 4; j++) o[i][j] = 0.f;
    }

    for (int kt = 0; kt <= qt; kt++) {
        __syncthreads();

        #pragma unroll
        for (int rr = 0; rr < 64; rr += 16) {
            const size_t gph = (size_t)(kt*64 + lrow + rr) * HEAD_DIM + lcol;
            *(float4*)&Ks[lrow + rr][lcol] = *(const float4*)(Kb + gph);
        }
        {
            const float* Vp = Vb + (size_t)(kt*64) * HEAD_DIM + vd;
            #pragma unroll
            for (int u = 0; u < 4; u++) {
                const int c = vcg*16 + u*4;
                float4 t;
                t.x = Vp[(size_t)(c+0) * HEAD_DIM];
                t.y = Vp[(size_t)(c+1) * HEAD_DIM];
                t.z = Vp[(size_t)(c+2) * HEAD_DIM];
                t.w = Vp[(size_t)(c+3) * HEAD_DIM];
                *(float4*)&Vt[vd][c] = t;
            }
        }
        __syncthreads();

        u64 s2[4][4];
        #pragma unroll
        for (int i = 0; i < 4; i++)
            #pragma unroll
            for (int j = 0; j < 4; j++) s2[i][j] = 0ull;

        #pragma unroll 4
        for (int d0 = 0; d0 < 64; d0 += 4) {
            float4 qa[4], kb[4];
            #pragma unroll
            for (int i = 0; i < 4; i++) qa[i] = *(const float4*)&Qs[R0+i][d0];
            #pragma unroll
            for (int j = 0; j < 4; j++) kb[j] = *(const float4*)&Ks[tx + 16*j][d0];
            u64 qu[4][2], ku[4][2];
            #pragma unroll
            for (int i = 0; i < 4; i++) {
                qu[i][0] = pk2(qa[i].x, qa[i].y);
                qu[i][1] = pk2(qa[i].z, qa[i].w);
            }
            #pragma unroll
            for (int j = 0; j < 4; j++) {
                ku[j][0] = pk2(kb[j].x, kb[j].y);
                ku[j][1] = pk2(kb[j].z, kb[j].w);
            }
            #pragma unroll
            for (int i = 0; i < 4; i++)
                #pragma unroll
                for (int j = 0; j < 4; j++) {
                    ffma2(s2[i][j], qu[i][0], ku[j][0]);
                    ffma2(s2[i][j], qu[i][1], ku[j][1]);
                }
        }

        float s[4][4];
        #pragma unroll
        for (int i = 0; i < 4; i++)
            #pragma unroll
            for (int j = 0; j < 4; j++) s[i][j] = hadd2(s2[i][j]);

        if (kt == qt) {
            #pragma unroll
            for (int i = 0; i < 4; i++)
                #pragma unroll
                for (int j = 0; j < 4; j++)
                    if (tx + 16*j > R0 + i) s[i][j] = -1e30f;
        }

        #pragma unroll
        for (int i = 0; i < 4; i++) {
            float mx = s[i][0];
            #pragma unroll
            for (int j = 1; j < 4; j++) mx = fmaxf(mx, s[i][j]);
            #pragma unroll
            for (int off = 1; off < 16; off <<= 1)
                mx = fmaxf(mx, __shfl_xor_sync(0xffffffffu, mx, off));
            const float mnew  = fmaxf(m_i[i], mx);
            const float alpha = __expf(m_i[i] - mnew);
            float rs = 0.f;
            #pragma unroll
            for (int j = 0; j < 4; j++) {
                const float p = __expf(s[i][j] - mnew);
                Ps[R0+i][tx + 16*j] = p;
                rs += p;
            }
            #pragma unroll
            for (int off = 1; off < 16; off <<= 1)
                rs += __shfl_xor_sync(0xffffffffu, rs, off);
            l_i[i] = l_i[i] * alpha + rs;
            m_i[i] = mnew;
            #pragma unroll
            for (int j = 0; j < 4; j++) o[i][j] *= alpha;
        }
        __syncthreads();

        u64 ot2[4][4];
        #pragma unroll
        for (int i = 0; i < 4; i++)
            #pragma unroll
            for (int j = 0; j < 4; j++) ot2[i][j] = 0ull;

        #pragma unroll 4
        for (int c0 = 0; c0 < 64; c0 += 4) {
            float4 pa[4], vb[4];
            #pragma unroll
            for (int i = 0; i < 4; i++) pa[i] = *(const float4*)&Ps[R0+i][c0];
            #pragma unroll
            for (int j = 0; j < 4; j++) vb[j] = *(const float4*)&Vt[tx + 16*j][c0];
            u64 pu[4][2], vu[4][2];
            #pragma unroll
            for (int i = 0; i < 4; i++) {
                pu[i][0] = pk2(pa[i].x, pa[i].y);
                pu[i][1] = pk2(pa[i].z, pa[i].w);
            }
            #pragma unroll
            for (int j = 0; j < 4; j++) {
                vu[j][0] = pk2(vb[j].x, vb[j].y);
                vu[j][1] = pk2(vb[j].z, vb[j].w);
            }
            #pragma unroll
            for (int i = 0; i < 4; i++)
                #pragma unroll
                for (int j = 0; j < 4; j++) {
                    ffma2(ot2[i][j], pu[i][0], vu[j][0]);
                    ffma2(ot2[i][j], pu[i][1], vu[j][1]);
                }
        }
        #pragma unroll
        for (int i = 0; i < 4; i++)
            #pragma unroll
            for (int j = 0; j < 4; j++) o[i][j] += hadd2(ot2[i][j]);
    }

    const int b = bh / HEADS, h = bh % HEADS;
    #pragma unroll
    for (int i = 0; i < 4; i++) {
        const int srow = q0 + R0 + i;
        const float inv = 1.0f / l_i[i];
        #pragma unroll
        for (int j = 0; j < 4; j++)
            Out[((size_t)(b*SEQ + srow))*EMBED + h*HEAD_DIM + tx + 16*j] = o[i][j] * inv;
    }
}

// ---------------------------------------------------------------------------
extern "C" void kernel_launch(void* const* d_in, const int* in_sizes, int n_in,
                              void* d_out, int out_size)
{
    const float* query  = (const float*)d_in[0];
    const float* key_in = (const float*)d_in[1];
    const float* value  = (const float*)d_in[2];
    // d_in[3] = causal mask (int32), known causal -> unused
    const float* Wq = (const float*)d_in[4];
    const float* bq = (const float*)d_in[5];
    const float* Wk = (const float*)d_in[6];
    const float* bk = (const float*)d_in[7];
    const float* Wv = (const float*)d_in[8];
    const float* bv = (const float*)d_in[9];
    const float* Wo = (const float*)d_in[10];
    const float* bo = (const float*)d_in[11];
    float* out = (float*)d_out;

    void *pq, *pk, *pv, *pa;
    cudaGetSymbolAddress(&pq, g_q);
    cudaGetSymbolAddress(&pk, g_k);
    cudaGetSymbolAddress(&pv, g_v);
    cudaGetSymbolAddress(&pa, g_attn);

    cudaFuncSetAttribute(flash_attn_kernel,
                         cudaFuncAttributeMaxDynamicSharedMemorySize, FA_SMEM);

    const dim3 gg(EMBED / GBN, M_TOT / GBM);   // (8, 64)
    const float qscale = 0.125f;               // 1/sqrt(HEAD_DIM)

    sgemm_tf32<0><<<gg, 256>>>(query,  Wq, bq, (float*)pq, qscale);
    sgemm_tf32<0><<<gg, 256>>>(key_in, Wk, bk, (float*)pk, 1.0f);
    sgemm_tf32<0><<<gg, 256>>>(value,  Wv, bv, (float*)pv, 1.0f);

    flash_attn_kernel<<<dim3(SEQ/64, BH), 256, FA_SMEM>>>(
        (const float*)pq, (const float*)pk, (const float*)pv, (float*)pa);

    sgemm_tf32<1><<<gg, 256>>>((const float*)pa, Wo, bo, out, 1.0f);
}

// round 11
// speedup vs baseline: 3.1700x; 1.0422x over previous
#include <cuda_runtime.h>

#define EMBED    1024
#define HEADS    16
#define HEAD_DIM 64
#define BATCH    4
#define SEQ      2048
#define M_TOT    (BATCH*SEQ)      // 8192 rows
#define BH       (BATCH*HEADS)    // 64 batch-heads
#define NQT      (SEQ/64)         // 32 q-tiles per bh

typedef unsigned long long u64;
typedef unsigned int u32;

// ---------------- packed f32x2 helpers (Blackwell FFMA2 path) --------------
__device__ __forceinline__ u64 pk2(float x, float y) {
    u64 r; asm("mov.b64 %0, {%1, %2};" : "=l"(r) : "f"(x), "f"(y)); return r;
}
__device__ __forceinline__ void upk2(float& x, float& y, u64 v) {
    asm("mov.b64 {%0, %1}, %2;" : "=f"(x), "=f"(y) : "l"(v));
}
__device__ __forceinline__ void ffma2(u64& d, u64 a, u64 b) {
    asm("fma.rn.f32x2 %0, %1, %2, %0;" : "+l"(d) : "l"(a), "l"(b));
}
__device__ __forceinline__ float hadd2(u64 v) {
    float x, y; upk2(x, y, v); return x + y;
}

// ---------------- tf32 helpers ---------------------------------------------
__device__ __forceinline__ u32 f2tf32(float x) {
    u32 r; asm("cvt.rna.tf32.f32 %0, %1;" : "=r"(r) : "f"(x)); return r;
}
__device__ __forceinline__ void mma_tf32(float* d, const u32* a, const u32* b) {
    asm volatile(
        "mma.sync.aligned.m16n8k8.row.col.f32.tf32.tf32.f32 "
        "{%0,%1,%2,%3}, {%4,%5,%6,%7}, {%8,%9}, {%0,%1,%2,%3};"
        : "+f"(d[0]), "+f"(d[1]), "+f"(d[2]), "+f"(d[3])
        : "r"(a[0]), "r"(a[1]), "r"(a[2]), "r"(a[3]), "r"(b[0]), "r"(b[1]));
}
__device__ __forceinline__ void cpa16(void* sdst, const void* gsrc) {
    u32 s = (u32)__cvta_generic_to_shared(sdst);
    asm volatile("cp.async.ca.shared.global [%0], [%1], 16;" :: "r"(s), "l"(gsrc));
}

// ---------------- scratch (device globals: allocation-free) ----------------
__device__ float g_q[BH * SEQ * HEAD_DIM];     // [b,h,s,d], pre-scaled by 1/sqrt(D)
__device__ float g_k[BH * SEQ * HEAD_DIM];     // [b,h,s,d]
__device__ float g_v[BH * SEQ * HEAD_DIM];     // [b,h,s,d]
__device__ float g_attn[M_TOT * EMBED];        // [b,s,e]

// ---------------- tf32 tensor-core GEMM-NT (unchanged from R10) -------------
#define GBM 128
#define GBN 128
#define GBK 16
#define GP  20
#define GNT (EMBED / GBK)

template<int MODE>
__global__ __launch_bounds__(256, 2) void sgemm_tf32(
    const float* __restrict__ A, const float* __restrict__ W,
    const float* __restrict__ bias, float* __restrict__ C, float scale)
{
    __shared__ float As[2][GBM][GP];
    __shared__ float Bs[2][GBN][GP];

    const int tid  = threadIdx.x;
    const int wid  = tid >> 5;
    const int lane = tid & 31;
    const int g    = lane >> 2;
    const int t4   = lane & 3;
    const int wm   = wid >> 2;
    const int wn   = wid & 3;
    const int m_base = wm * 64;
    const int n_base = wn * 32;

    const int row_blk = blockIdx.y * GBM;
    const int col_blk = blockIdx.x * GBN;

    const float* Ag = A + (size_t)row_blk * EMBED;
    const float* Bg = W + (size_t)col_blk * EMBED;

    const int cr = tid >> 2;
    const int cc = (tid & 3) * 4;

    float acc[4][4][4];
    #pragma unroll
    for (int mt = 0; mt < 4; mt++)
        #pragma unroll
        for (int nt = 0; nt < 4; nt++)
            #pragma unroll
            for (int r = 0; r < 4; r++) acc[mt][nt][r] = 0.f;

    {
        const float* ap = Ag + (size_t)cr * EMBED + cc;
        const float* bp = Bg + (size_t)cr * EMBED + cc;
        cpa16(&As[0][cr][cc],      ap);
        cpa16(&As[0][cr + 64][cc], ap + (size_t)64 * EMBED);
        cpa16(&Bs[0][cr][cc],      bp);
        cpa16(&Bs[0][cr + 64][cc], bp + (size_t)64 * EMBED);
        asm volatile("cp.async.commit_group;" ::: "memory");
    }

    for (int t = 0; t < GNT; t++) {
        const int s = t & 1;
        if (t + 1 < GNT) {
            const int sn = (t + 1) & 1;
            const float* ap = Ag + (size_t)cr * EMBED + (t + 1) * GBK + cc;
            const float* bp = Bg + (size_t)cr * EMBED + (t + 1) * GBK + cc;
            cpa16(&As[sn][cr][cc],      ap);
            cpa16(&As[sn][cr + 64][cc], ap + (size_t)64 * EMBED);
            cpa16(&Bs[sn][cr][cc],      bp);
            cpa16(&Bs[sn][cr + 64][cc], bp + (size_t)64 * EMBED);
            asm volatile("cp.async.commit_group;" ::: "memory");
            asm volatile("cp.async.wait_group 1;" ::: "memory");
        } else {
            asm volatile("cp.async.wait_group 0;" ::: "memory");
        }
        __syncthreads();

        #pragma unroll
        for (int kk = 0; kk < GBK; kk += 8) {
            u32 a[4][4], b[4][2];
            #pragma unroll
            for (int mt = 0; mt < 4; mt++) {
                const float* p = &As[s][m_base + mt*16 + g][kk + t4];
                a[mt][0] = f2tf32(p[0]);
                a[mt][1] = f2tf32(p[8 * GP]);
                a[mt][2] = f2tf32(p[4]);
                a[mt][3] = f2tf32(p[8 * GP + 4]);
            }
            #pragma unroll
            for (int nt = 0; nt < 4; nt++) {
                const float* p = &Bs[s][n_base + nt*8 + g][kk + t4];
                b[nt][0] = f2tf32(p[0]);
                b[nt][1] = f2tf32(p[4]);
            }
            #pragma unroll
            for (int mt = 0; mt < 4; mt++)
                #pragma unroll
                for (int nt = 0; nt < 4; nt++)
                    mma_tf32(acc[mt][nt], a[mt], b[nt]);
        }
        __syncthreads();
    }

    #pragma unroll
    for (int mt = 0; mt < 4; mt++) {
        #pragma unroll
        for (int nt = 0; nt < 4; nt++) {
            const int c0 = col_blk + n_base + nt*8 + 2*t4;
            const float bia0 = bias[c0], bia1 = bias[c0 + 1];
            #pragma unroll
            for (int half = 0; half < 2; half++) {
                const int r = row_blk + m_base + mt*16 + g + half*8;
                float v0 = acc[mt][nt][half*2 + 0] + bia0;
                float v1 = acc[mt][nt][half*2 + 1] + bia1;
                if (MODE == 0) {
                    v0 *= scale; v1 *= scale;
                    const int bb = r / SEQ, ss = r % SEQ;
                    const int h = c0 / HEAD_DIM, d = c0 % HEAD_DIM;
                    float* dst = &((float*)C)[(((size_t)(bb*HEADS + h))*SEQ + ss)*HEAD_DIM + d];
                    *(float2*)dst = make_float2(v0, v1);
                } else {
                    *(float2*)&C[(size_t)r * EMBED + c0] = make_float2(v0, v1);
                }
            }
        }
    }
}

// ---------------- Flash attention (causal), Br=Bc=64, D=64 -----------------
// Mirror-pair load balancing: block `pair` processes qt = NQT-1-pair (long,
// first) then qt = pair (short). Every block does exactly NQT+1 k-tiles.
// Inner loops identical to the measured-good R9/R10 version.
#define PADW 68
#define FA_SMEM (4 * 64 * PADW * (int)sizeof(float))   // 69632 B

__global__ __launch_bounds__(256) void flash_attn_kernel(
    const float* __restrict__ Q, const float* __restrict__ K,
    const float* __restrict__ V, float* __restrict__ Out)
{
    extern __shared__ float sm[];
    float (*Qs)[PADW] = (float(*)[PADW])(sm);
    float (*Ks)[PADW] = (float(*)[PADW])(sm + 64*PADW);
    float (*Vt)[PADW] = (float(*)[PADW])(sm + 2*64*PADW);   // [d][c] transposed
    float (*Ps)[PADW] = (float(*)[PADW])(sm + 3*64*PADW);

    const int bh   = blockIdx.y;
    const int pair = blockIdx.x;        // 0..NQT/2-1

    const float* Qb = Q + (size_t)bh * SEQ * HEAD_DIM;
    const float* Kb = K + (size_t)bh * SEQ * HEAD_DIM;
    const float* Vb = V + (size_t)bh * SEQ * HEAD_DIM;

    const int tid = threadIdx.x;
    const int tx = tid & 15;
    const int ty = tid >> 4;
    const int R0 = ty * 4;

    const int lrow = tid >> 4;          // 0..15
    const int lcol = (tid & 15) * 4;    // 0..60
    const int vd  = tid & 63;
    const int vcg = tid >> 6;

    const int b = bh / HEADS, h = bh % HEADS;

    #pragma unroll 1
    for (int pass = 0; pass < 2; pass++) {
        const int qt = pass ? pair : (NQT - 1 - pair);   // long tile first
        const int q0 = qt * 64;

        __syncthreads();   // Qs (and Ks/Vt/Ps) free from previous pass readers

        // load Q tile
        #pragma unroll
        for (int rr = 0; rr < 64; rr += 16) {
            float4 v = *(const float4*)(Qb + (size_t)(q0 + lrow + rr) * HEAD_DIM + lcol);
            *(float4*)&Qs[lrow + rr][lcol] = v;
        }

        float m_i[4], l_i[4], o[4][4];
        #pragma unroll
        for (int i = 0; i < 4; i++) {
            m_i[i] = -1e30f; l_i[i] = 0.f;
            #pragma unroll
            for (int j = 0; j < 4; j++) o[i][j] = 0.f;
        }

        for (int kt = 0; kt <= qt; kt++) {
            __syncthreads();   // protect Ks/Vt/Ps from previous iteration readers

            #pragma unroll
            for (int rr = 0; rr < 64; rr += 16) {
                const size_t gph = (size_t)(kt*64 + lrow + rr) * HEAD_DIM + lcol;
                *(float4*)&Ks[lrow + rr][lcol] = *(const float4*)(Kb + gph);
            }
            {
                const float* Vp = Vb + (size_t)(kt*64) * HEAD_DIM + vd;
                #pragma unroll
                for (int u = 0; u < 4; u++) {
                    const int c = vcg*16 + u*4;
                    float4 t;
                    t.x = Vp[(size_t)(c+0) * HEAD_DIM];
                    t.y = Vp[(size_t)(c+1) * HEAD_DIM];
                    t.z = Vp[(size_t)(c+2) * HEAD_DIM];
                    t.w = Vp[(size_t)(c+3) * HEAD_DIM];
                    *(float4*)&Vt[vd][c] = t;
                }
            }
            __syncthreads();

            // scores S = Q K^T, packed f32x2 over d
            u64 s2[4][4];
            #pragma unroll
            for (int i = 0; i < 4; i++)
                #pragma unroll
                for (int j = 0; j < 4; j++) s2[i][j] = 0ull;

            #pragma unroll 4
            for (int d0 = 0; d0 < 64; d0 += 4) {
                float4 qa[4], kb[4];
                #pragma unroll
                for (int i = 0; i < 4; i++) qa[i] = *(const float4*)&Qs[R0+i][d0];
                #pragma unroll
                for (int j = 0; j < 4; j++) kb[j] = *(const float4*)&Ks[tx + 16*j][d0];
                u64 qu[4][2], ku[4][2];
                #pragma unroll
                for (int i = 0; i < 4; i++) {
                    qu[i][0] = pk2(qa[i].x, qa[i].y);
                    qu[i][1] = pk2(qa[i].z, qa[i].w);
                }
                #pragma unroll
                for (int j = 0; j < 4; j++) {
                    ku[j][0] = pk2(kb[j].x, kb[j].y);
                    ku[j][1] = pk2(kb[j].z, kb[j].w);
                }
                #pragma unroll
                for (int i = 0; i < 4; i++)
                    #pragma unroll
                    for (int j = 0; j < 4; j++) {
                        ffma2(s2[i][j], qu[i][0], ku[j][0]);
                        ffma2(s2[i][j], qu[i][1], ku[j][1]);
                    }
            }

            float s[4][4];
            #pragma unroll
            for (int i = 0; i < 4; i++)
                #pragma unroll
                for (int j = 0; j < 4; j++) s[i][j] = hadd2(s2[i][j]);

            if (kt == qt) {
                #pragma unroll
                for (int i = 0; i < 4; i++)
                    #pragma unroll
                    for (int j = 0; j < 4; j++)
                        if (tx + 16*j > R0 + i) s[i][j] = -1e30f;
            }

            // online softmax
            #pragma unroll
            for (int i = 0; i < 4; i++) {
                float mx = s[i][0];
                #pragma unroll
                for (int j = 1; j < 4; j++) mx = fmaxf(mx, s[i][j]);
                #pragma unroll
                for (int off = 1; off < 16; off <<= 1)
                    mx = fmaxf(mx, __shfl_xor_sync(0xffffffffu, mx, off));
                const float mnew  = fmaxf(m_i[i], mx);
                const float alpha = __expf(m_i[i] - mnew);
                float rs = 0.f;
                #pragma unroll
                for (int j = 0; j < 4; j++) {
                    const float p = __expf(s[i][j] - mnew);
                    Ps[R0+i][tx + 16*j] = p;
                    rs += p;
                }
                #pragma unroll
                for (int off = 1; off < 16; off <<= 1)
                    rs += __shfl_xor_sync(0xffffffffu, rs, off);
                l_i[i] = l_i[i] * alpha + rs;
                m_i[i] = mnew;
                #pragma unroll
                for (int j = 0; j < 4; j++) o[i][j] *= alpha;
            }
            __syncthreads();

            // O += P @ V (packed over c, V transposed)
            u64 ot2[4][4];
            #pragma unroll
            for (int i = 0; i < 4; i++)
                #pragma unroll
                for (int j = 0; j < 4; j++) ot2[i][j] = 0ull;

            #pragma unroll 4
            for (int c0 = 0; c0 < 64; c0 += 4) {
                float4 pa[4], vb[4];
                #pragma unroll
                for (int i = 0; i < 4; i++) pa[i] = *(const float4*)&Ps[R0+i][c0];
                #pragma unroll
                for (int j = 0; j < 4; j++) vb[j] = *(const float4*)&Vt[tx + 16*j][c0];
                u64 pu[4][2], vu[4][2];
                #pragma unroll
                for (int i = 0; i < 4; i++) {
                    pu[i][0] = pk2(pa[i].x, pa[i].y);
                    pu[i][1] = pk2(pa[i].z, pa[i].w);
                }
                #pragma unroll
                for (int j = 0; j < 4; j++) {
                    vu[j][0] = pk2(vb[j].x, vb[j].y);
                    vu[j][1] = pk2(vb[j].z, vb[j].w);
                }
                #pragma unroll
                for (int i = 0; i < 4; i++)
                    #pragma unroll
                    for (int j = 0; j < 4; j++) {
                        ffma2(ot2[i][j], pu[i][0], vu[j][0]);
                        ffma2(ot2[i][j], pu[i][1], vu[j][1]);
                    }
            }
            #pragma unroll
            for (int i = 0; i < 4; i++)
                #pragma unroll
                for (int j = 0; j < 4; j++) o[i][j] += hadd2(ot2[i][j]);
        }

        // write back to [b, s, h*64 + (tx+16j)]
        #pragma unroll
        for (int i = 0; i < 4; i++) {
            const int srow = q0 + R0 + i;
            const float inv = 1.0f / l_i[i];
            #pragma unroll
            for (int j = 0; j < 4; j++)
                Out[((size_t)(b*SEQ + srow))*EMBED + h*HEAD_DIM + tx + 16*j] = o[i][j] * inv;
        }
    }
}

// ---------------------------------------------------------------------------
extern "C" void kernel_launch(void* const* d_in, const int* in_sizes, int n_in,
                              void* d_out, int out_size)
{
    const float* query  = (const float*)d_in[0];
    const float* key_in = (const float*)d_in[1];
    const float* value  = (const float*)d_in[2];
    // d_in[3] = causal mask (int32), known causal -> unused
    const float* Wq = (const float*)d_in[4];
    const float* bq = (const float*)d_in[5];
    const float* Wk = (const float*)d_in[6];
    const float* bk = (const float*)d_in[7];
    const float* Wv = (const float*)d_in[8];
    const float* bv = (const float*)d_in[9];
    const float* Wo = (const float*)d_in[10];
    const float* bo = (const float*)d_in[11];
    float* out = (float*)d_out;

    void *pq, *pk, *pv, *pa;
    cudaGetSymbolAddress(&pq, g_q);
    cudaGetSymbolAddress(&pk, g_k);
    cudaGetSymbolAddress(&pv, g_v);
    cudaGetSymbolAddress(&pa, g_attn);

    cudaFuncSetAttribute(flash_attn_kernel,
                         cudaFuncAttributeMaxDynamicSharedMemorySize, FA_SMEM);

    const dim3 gg(EMBED / GBN, M_TOT / GBM);   // (8, 64)
    const float qscale = 0.125f;               // 1/sqrt(HEAD_DIM)

    sgemm_tf32<0><<<gg, 256>>>(query,  Wq, bq, (float*)pq, qscale);
    sgemm_tf32<0><<<gg, 256>>>(key_in, Wk, bk, (float*)pk, 1.0f);
    sgemm_tf32<0><<<gg, 256>>>(value,  Wv, bv, (float*)pv, 1.0f);

    flash_attn_kernel<<<dim3(NQT/2, BH), 256, FA_SMEM>>>(
        (const float*)pq, (const float*)pk, (const float*)pv, (float*)pa);

    sgemm_tf32<1><<<gg, 256>>>((const float*)pa, Wo, bo, out, 1.0f);
}